// round 5
// baseline (speedup 1.0000x reference)
#include <cuda_runtime.h>
#include <math.h>

// ---------------------------------------------------------------------------
// IGAB block, B=4, C=128, H=W=256, window 8x8, heads=8, head_dim=16, HIDDEN=512
// fp32 baseline, fully fused per stage:
//   k1: LN1 + QKV + gate + window-attention + proj + residual  -> d_out ("out")
//   k2: LN2 + W1 + GELU                                        -> g_h1
//   k3: depthwise 3x3 + bias + GELU                            -> g_h2
//   k4: W2 + bias + residual (in-place on d_out)               -> d_out (final)
// ---------------------------------------------------------------------------

#define HW 65536            // 256*256
#define NPLANE 256

// scratch (device globals: no cudaMalloc allowed)
__device__ float g_h1[(size_t)4 * 512 * HW];   // 512 MB
__device__ float g_h2[(size_t)4 * 512 * HW];   // 512 MB

// ----- kernel 1 shared layout (floats) -----
#define OFF_A   0        // raw x tile   [128][68]
#define OFF_B   8704     // xn, later attn-out (os) [128][68]
#define OFF_Q   17408    // q [128][68]
#define OFF_K   26112    // k [128][68]
#define OFF_V   34816    // v [128][68]
#define OFF_W   43520    // weight chunk [64][132]
#define OFF_S   51968    // scores / staging [64][68]
#define OFF_L0  56320
#define OFF_MU  56384
#define OFF_RS  56448
#define OFF_DEN 56512
#define SM1_FLOATS 56576
#define SM1_BYTES (SM1_FLOATS * 4)

__device__ __forceinline__ float gelu_exact(float v) {
    return 0.5f * v * (1.0f + erff(v * 0.70710678118654752f));
}

__global__ __launch_bounds__(256, 1)
void k1_attn(const float* __restrict__ x, const float* __restrict__ l0,
             const float* __restrict__ n1w, const float* __restrict__ n1b,
             const float* __restrict__ qkvw, const float* __restrict__ gw,
             const float* __restrict__ gb, const float* __restrict__ pw,
             const float* __restrict__ pb, float* __restrict__ outp)
{
    extern __shared__ float sm[];
    const int tid = threadIdx.x;
    const int wi = blockIdx.x;           // window id: b*1024 + hi*32 + wj
    const int b  = wi >> 10;
    const int hi = (wi >> 5) & 31;
    const int wj = wi & 31;
    const int base_pix = (hi * 8) * NPLANE + wj * 8;
    const float* xb = x + (size_t)b * 128 * HW;

    // load raw x tile [128 ch][64 px], px = i*8+j
    #pragma unroll
    for (int it = 0; it < 32; ++it) {
        int idx = tid + it * 256;
        int c = idx >> 6, p = idx & 63;
        sm[OFF_A + c * 68 + p] = xb[c * HW + base_pix + (p >> 3) * NPLANE + (p & 7)];
    }
    if (tid < 64) {
        int p = tid;
        sm[OFF_L0 + p] = l0[(size_t)b * HW + base_pix + (p >> 3) * NPLANE + (p & 7)];
    }
    __syncthreads();

    // LN1 stats: 4 threads per pixel
    {
        int p = tid >> 2, part = tid & 3;
        float s = 0.f, sq = 0.f;
        #pragma unroll
        for (int c = part * 32; c < part * 32 + 32; ++c) {
            float v = sm[OFF_A + c * 68 + p];
            s += v; sq += v * v;
        }
        s  += __shfl_xor_sync(0xffffffffu, s, 1);
        sq += __shfl_xor_sync(0xffffffffu, sq, 1);
        s  += __shfl_xor_sync(0xffffffffu, s, 2);
        sq += __shfl_xor_sync(0xffffffffu, sq, 2);
        if (part == 0) {
            float mu = s * (1.f / 128.f);
            float var = sq * (1.f / 128.f) - mu * mu;
            sm[OFF_MU + p] = mu;
            sm[OFF_RS + p] = rsqrtf(var + 1e-6f);
        }
    }
    __syncthreads();
    // normalize into B
    #pragma unroll
    for (int it = 0; it < 32; ++it) {
        int idx = tid + it * 256;
        int c = idx >> 6, p = idx & 63;
        sm[OFF_B + c * 68 + p] =
            n1w[c] * (sm[OFF_A + c * 68 + p] - sm[OFF_MU + p]) * sm[OFF_RS + p] + n1b[c];
    }
    __syncthreads();

    const int tx = tid & 15, ty = tid >> 4;

    // ---- QKV: 6 output chunks of 64 ----
    for (int ch = 0; ch < 6; ++ch) {
        #pragma unroll
        for (int it = 0; it < 32; ++it) {
            int idx = tid + it * 256;
            int ol = idx >> 7, c = idx & 127;
            sm[OFF_W + ol * 132 + c] = qkvw[(ch * 64 + ol) * 128 + c];
        }
        __syncthreads();
        float acc[4][4];
        #pragma unroll
        for (int i = 0; i < 4; ++i)
            #pragma unroll
            for (int j = 0; j < 4; ++j) acc[i][j] = 0.f;
        #pragma unroll 4
        for (int c = 0; c < 128; ++c) {
            float4 xv = *(const float4*)&sm[OFF_B + c * 68 + 4 * tx];
            float xa[4] = {xv.x, xv.y, xv.z, xv.w};
            float wa[4];
            #pragma unroll
            for (int j = 0; j < 4; ++j) wa[j] = sm[OFF_W + (4 * ty + j) * 132 + c];
            #pragma unroll
            for (int i = 0; i < 4; ++i)
                #pragma unroll
                for (int j = 0; j < 4; ++j) acc[i][j] += xa[i] * wa[j];
        }
        int dst = (ch < 2) ? OFF_Q : (ch < 4) ? OFF_K : OFF_V;
        int rbase = (ch & 1) * 64;
        if (ch < 2) {
            #pragma unroll
            for (int j = 0; j < 4; ++j) {
                int o = rbase + 4 * ty + j;
                float gwv = gw[o], gbv = gb[o];
                float4 st;
                float* pst = &st.x;
                #pragma unroll
                for (int i = 0; i < 4; ++i) {
                    int p = 4 * tx + i;
                    float z = sm[OFF_L0 + p] * gwv + gbv;
                    float g = 1.f / (1.f + __expf(-z));
                    pst[i] = acc[i][j] * g;
                }
                *(float4*)&sm[dst + o * 68 + 4 * tx] = st;
            }
        } else {
            #pragma unroll
            for (int j = 0; j < 4; ++j) {
                int o = rbase + 4 * ty + j;
                float4 st = {acc[0][j], acc[1][j], acc[2][j], acc[3][j]};
                *(float4*)&sm[dst + o * 68 + 4 * tx] = st;
            }
        }
        __syncthreads();
    }

    // ---- window attention, head-sequential ----
    for (int h = 0; h < 8; ++h) {
        const int cb = h * 16;
        {   // S = scale * Q K^T  (64x64, k=16)
            float acc[4][4];
            #pragma unroll
            for (int i = 0; i < 4; ++i)
                #pragma unroll
                for (int j = 0; j < 4; ++j) acc[i][j] = 0.f;
            #pragma unroll
            for (int d = 0; d < 16; ++d) {
                float4 qv = *(const float4*)&sm[OFF_Q + (cb + d) * 68 + 4 * tx];
                float4 kv = *(const float4*)&sm[OFF_K + (cb + d) * 68 + 4 * ty];
                float qa[4] = {qv.x, qv.y, qv.z, qv.w};
                float ka[4] = {kv.x, kv.y, kv.z, kv.w};
                #pragma unroll
                for (int i = 0; i < 4; ++i)
                    #pragma unroll
                    for (int j = 0; j < 4; ++j) acc[i][j] += qa[i] * ka[j];
            }
            #pragma unroll
            for (int i = 0; i < 4; ++i) {
                float4 st = {acc[i][0] * 0.25f, acc[i][1] * 0.25f,
                             acc[i][2] * 0.25f, acc[i][3] * 0.25f};
                *(float4*)&sm[OFF_S + (4 * tx + i) * 68 + 4 * ty] = st;
            }
        }
        __syncthreads();
        {   // softmax over rows (4 threads / row)
            int r = tid >> 2, part = tid & 3;
            float m = -1e30f;
            #pragma unroll
            for (int kk = part * 16; kk < part * 16 + 16; ++kk)
                m = fmaxf(m, sm[OFF_S + r * 68 + kk]);
            m = fmaxf(m, __shfl_xor_sync(0xffffffffu, m, 1));
            m = fmaxf(m, __shfl_xor_sync(0xffffffffu, m, 2));
            float s = 0.f;
            #pragma unroll
            for (int kk = part * 16; kk < part * 16 + 16; ++kk) {
                float e = __expf(sm[OFF_S + r * 68 + kk] - m);
                sm[OFF_S + r * 68 + kk] = e;
                s += e;
            }
            s += __shfl_xor_sync(0xffffffffu, s, 1);
            s += __shfl_xor_sync(0xffffffffu, s, 2);
            if (part == 0) sm[OFF_DEN + r] = 1.f / s;
        }
        __syncthreads();
        {   // O = P V  (64x16), write into B as [c][p]
            int pq = tid >> 2, dg = tid & 3;
            float a0 = 0.f, a1 = 0.f, a2 = 0.f, a3 = 0.f;
            #pragma unroll 4
            for (int kk = 0; kk < 64; ++kk) {
                float pr = sm[OFF_S + pq * 68 + kk];
                a0 += pr * sm[OFF_V + (cb + 4 * dg + 0) * 68 + kk];
                a1 += pr * sm[OFF_V + (cb + 4 * dg + 1) * 68 + kk];
                a2 += pr * sm[OFF_V + (cb + 4 * dg + 2) * 68 + kk];
                a3 += pr * sm[OFF_V + (cb + 4 * dg + 3) * 68 + kk];
            }
            float dn = sm[OFF_DEN + pq];
            sm[OFF_B + (cb + 4 * dg + 0) * 68 + pq] = a0 * dn;
            sm[OFF_B + (cb + 4 * dg + 1) * 68 + pq] = a1 * dn;
            sm[OFF_B + (cb + 4 * dg + 2) * 68 + pq] = a2 * dn;
            sm[OFF_B + (cb + 4 * dg + 3) * 68 + pq] = a3 * dn;
        }
        __syncthreads();
    }

    // ---- proj + bias + residual, staged coalesced store ----
    for (int ch = 0; ch < 2; ++ch) {
        #pragma unroll
        for (int it = 0; it < 32; ++it) {
            int idx = tid + it * 256;
            int ol = idx >> 7, c = idx & 127;
            sm[OFF_W + ol * 132 + c] = pw[(ch * 64 + ol) * 128 + c];
        }
        __syncthreads();
        float acc[4][4];
        #pragma unroll
        for (int i = 0; i < 4; ++i)
            #pragma unroll
            for (int j = 0; j < 4; ++j) acc[i][j] = 0.f;
        #pragma unroll 4
        for (int c = 0; c < 128; ++c) {
            float4 xv = *(const float4*)&sm[OFF_B + c * 68 + 4 * tx];
            float xa[4] = {xv.x, xv.y, xv.z, xv.w};
            float wa[4];
            #pragma unroll
            for (int j = 0; j < 4; ++j) wa[j] = sm[OFF_W + (4 * ty + j) * 132 + c];
            #pragma unroll
            for (int i = 0; i < 4; ++i)
                #pragma unroll
                for (int j = 0; j < 4; ++j) acc[i][j] += xa[i] * wa[j];
        }
        #pragma unroll
        for (int j = 0; j < 4; ++j) {
            float4 st = {acc[0][j], acc[1][j], acc[2][j], acc[3][j]};
            *(float4*)&sm[OFF_S + (4 * ty + j) * 68 + 4 * tx] = st;
        }
        __syncthreads();
        #pragma unroll
        for (int it = 0; it < 16; ++it) {
            int idx = tid + it * 256;
            int ol = idx >> 6, p = idx & 63;
            int o = ch * 64 + ol;
            float v = sm[OFF_S + ol * 68 + p] + pb[o] + sm[OFF_A + o * 68 + p];
            outp[(size_t)(b * 128 + o) * HW + base_pix + (p >> 3) * NPLANE + (p & 7)] = v;
        }
        __syncthreads();
    }
}

// ----- kernel 2: LN2 + W1(128->512) + GELU -----
#define SM2_XS 0
#define SM2_WS 8704
#define SM2_SS 17152
#define SM2_MU 21504
#define SM2_RS 21568
#define SM2_FLOATS 21632
#define SM2_BYTES (SM2_FLOATS * 4)

__global__ __launch_bounds__(256, 2)
void k2_ffn1(const float* __restrict__ inp, const float* __restrict__ n2w,
             const float* __restrict__ n2b, const float* __restrict__ w1,
             const float* __restrict__ b1)
{
    extern __shared__ float sm[];
    const int tid = threadIdx.x;
    const int pg = blockIdx.x * 64;
    const int b = pg >> 16;
    const int pix = pg & 65535;
    const float* ib = inp + (size_t)b * 128 * HW + pix;

    #pragma unroll
    for (int it = 0; it < 32; ++it) {
        int idx = tid + it * 256;
        int c = idx >> 6, p = idx & 63;
        sm[SM2_XS + c * 68 + p] = ib[c * HW + p];
    }
    __syncthreads();
    {
        int p = tid >> 2, part = tid & 3;
        float s = 0.f, sq = 0.f;
        #pragma unroll
        for (int c = part * 32; c < part * 32 + 32; ++c) {
            float v = sm[SM2_XS + c * 68 + p];
            s += v; sq += v * v;
        }
        s  += __shfl_xor_sync(0xffffffffu, s, 1);
        sq += __shfl_xor_sync(0xffffffffu, sq, 1);
        s  += __shfl_xor_sync(0xffffffffu, s, 2);
        sq += __shfl_xor_sync(0xffffffffu, sq, 2);
        if (part == 0) {
            float mu = s * (1.f / 128.f);
            float var = sq * (1.f / 128.f) - mu * mu;
            sm[SM2_MU + p] = mu;
            sm[SM2_RS + p] = rsqrtf(var + 1e-6f);
        }
    }
    __syncthreads();
    #pragma unroll
    for (int it = 0; it < 32; ++it) {
        int idx = tid + it * 256;
        int c = idx >> 6, p = idx & 63;
        sm[SM2_XS + c * 68 + p] =
            n2w[c] * (sm[SM2_XS + c * 68 + p] - sm[SM2_MU + p]) * sm[SM2_RS + p] + n2b[c];
    }
    __syncthreads();

    const int tx = tid & 15, ty = tid >> 4;
    for (int ch = 0; ch < 8; ++ch) {
        #pragma unroll
        for (int it = 0; it < 32; ++it) {
            int idx = tid + it * 256;
            int ol = idx >> 7, c = idx & 127;
            sm[SM2_WS + ol * 132 + c] = w1[(ch * 64 + ol) * 128 + c];
        }
        __syncthreads();
        float acc[4][4];
        #pragma unroll
        for (int i = 0; i < 4; ++i)
            #pragma unroll
            for (int j = 0; j < 4; ++j) acc[i][j] = 0.f;
        #pragma unroll 4
        for (int c = 0; c < 128; ++c) {
            float4 xv = *(const float4*)&sm[SM2_XS + c * 68 + 4 * tx];
            float xa[4] = {xv.x, xv.y, xv.z, xv.w};
            float wa[4];
            #pragma unroll
            for (int j = 0; j < 4; ++j) wa[j] = sm[SM2_WS + (4 * ty + j) * 132 + c];
            #pragma unroll
            for (int i = 0; i < 4; ++i)
                #pragma unroll
                for (int j = 0; j < 4; ++j) acc[i][j] += xa[i] * wa[j];
        }
        #pragma unroll
        for (int j = 0; j < 4; ++j) {
            int o = ch * 64 + 4 * ty + j;
            float bv = b1[o];
            float4 st = {gelu_exact(acc[0][j] + bv), gelu_exact(acc[1][j] + bv),
                         gelu_exact(acc[2][j] + bv), gelu_exact(acc[3][j] + bv)};
            *(float4*)&sm[SM2_SS + (4 * ty + j) * 68 + 4 * tx] = st;
        }
        __syncthreads();
        #pragma unroll
        for (int it = 0; it < 16; ++it) {
            int idx = tid + it * 256;
            int ol = idx >> 6, p = idx & 63;
            g_h1[(size_t)(b * 512 + ch * 64 + ol) * HW + pix + p] = sm[SM2_SS + ol * 68 + p];
        }
        __syncthreads();
    }
}

// ----- kernel 3: depthwise 3x3 + bias + GELU -----
__global__ __launch_bounds__(256)
void k3_dw(const float* __restrict__ dw, const float* __restrict__ dwb)
{
    __shared__ float tile[10][34];
    const int plane = blockIdx.z;            // b*512 + ch
    const int ch = plane & 511;
    const float* ip = g_h1 + (size_t)plane * HW;
    float* op = g_h2 + (size_t)plane * HW;
    const int x0 = blockIdx.x * 32, y0 = blockIdx.y * 8;
    const int tid = threadIdx.x;

    for (int idx = tid; idx < 340; idx += 256) {
        int ly = idx / 34, lx = idx % 34;
        int gy = y0 + ly - 1, gx = x0 + lx - 1;
        tile[ly][lx] = (gy >= 0 && gy < 256 && gx >= 0 && gx < 256) ? ip[gy * NPLANE + gx] : 0.f;
    }
    __syncthreads();

    const int tx = tid & 31, ty = tid >> 5;
    float w[9];
    #pragma unroll
    for (int i = 0; i < 9; ++i) w[i] = dw[ch * 9 + i];
    float s = dwb[ch];
    #pragma unroll
    for (int dy = 0; dy < 3; ++dy)
        #pragma unroll
        for (int dx = 0; dx < 3; ++dx)
            s += w[dy * 3 + dx] * tile[ty + dy][tx + dx];
    op[(y0 + ty) * NPLANE + x0 + tx] = gelu_exact(s);
}

// ----- kernel 4: W2(512->128) + bias + residual (in-place on d_out) -----
#define SM4_HS 0
#define SM4_WS 34816
#define SM4_SS 43264
#define SM4_FLOATS 47616
#define SM4_BYTES (SM4_FLOATS * 4)

__global__ __launch_bounds__(256, 1)
void k4_ffn2(const float* __restrict__ w2, const float* __restrict__ b2,
             float* __restrict__ io)
{
    extern __shared__ float sm[];
    const int tid = threadIdx.x;
    const int pg = blockIdx.x * 64;
    const int b = pg >> 16;
    const int pix = pg & 65535;
    const float* hb = g_h2 + (size_t)b * 512 * HW + pix;

    #pragma unroll 8
    for (int it = 0; it < 128; ++it) {
        int idx = tid + it * 256;
        int c = idx >> 6, p = idx & 63;
        sm[SM4_HS + c * 68 + p] = hb[(size_t)c * HW + p];
    }
    __syncthreads();

    const int tx = tid & 15, ty = tid >> 4;
    for (int och = 0; och < 2; ++och) {
        float acc[4][4];
        #pragma unroll
        for (int i = 0; i < 4; ++i)
            #pragma unroll
            for (int j = 0; j < 4; ++j) acc[i][j] = 0.f;
        for (int kch = 0; kch < 4; ++kch) {
            #pragma unroll
            for (int it = 0; it < 32; ++it) {
                int idx = tid + it * 256;
                int ol = idx >> 7, c = idx & 127;
                sm[SM4_WS + ol * 132 + c] = w2[(och * 64 + ol) * 512 + kch * 128 + c];
            }
            __syncthreads();
            #pragma unroll 4
            for (int c = 0; c < 128; ++c) {
                float4 xv = *(const float4*)&sm[SM4_HS + (kch * 128 + c) * 68 + 4 * tx];
                float xa[4] = {xv.x, xv.y, xv.z, xv.w};
                float wa[4];
                #pragma unroll
                for (int j = 0; j < 4; ++j) wa[j] = sm[SM4_WS + (4 * ty + j) * 132 + c];
                #pragma unroll
                for (int i = 0; i < 4; ++i)
                    #pragma unroll
                    for (int j = 0; j < 4; ++j) acc[i][j] += xa[i] * wa[j];
            }
            __syncthreads();
        }
        #pragma unroll
        for (int j = 0; j < 4; ++j) {
            float4 st = {acc[0][j], acc[1][j], acc[2][j], acc[3][j]};
            *(float4*)&sm[SM4_SS + (4 * ty + j) * 68 + 4 * tx] = st;
        }
        __syncthreads();
        #pragma unroll
        for (int it = 0; it < 16; ++it) {
            int idx = tid + it * 256;
            int ol = idx >> 6, p = idx & 63;
            int o = och * 64 + ol;
            size_t ad = (size_t)(b * 128 + o) * HW + pix + p;
            io[ad] = io[ad] + sm[SM4_SS + ol * 68 + p] + b2[o];
        }
        __syncthreads();
    }
}

// ---------------------------------------------------------------------------
extern "C" void kernel_launch(void* const* d_in, const int* in_sizes, int n_in,
                              void* d_out, int out_size)
{
    const float* x    = (const float*)d_in[0];
    const float* l0   = (const float*)d_in[1];
    const float* n1w  = (const float*)d_in[2];
    const float* n1b  = (const float*)d_in[3];
    const float* n2w  = (const float*)d_in[4];
    const float* n2b  = (const float*)d_in[5];
    const float* qkvw = (const float*)d_in[6];
    const float* gw   = (const float*)d_in[7];
    const float* gb   = (const float*)d_in[8];
    const float* pw   = (const float*)d_in[9];
    const float* pb   = (const float*)d_in[10];
    const float* w1   = (const float*)d_in[11];
    const float* b1   = (const float*)d_in[12];
    const float* dw   = (const float*)d_in[13];
    const float* dwb  = (const float*)d_in[14];
    const float* w2   = (const float*)d_in[15];
    const float* b2   = (const float*)d_in[16];
    float* out = (float*)d_out;

    cudaFuncSetAttribute(k1_attn, cudaFuncAttributeMaxDynamicSharedMemorySize, SM1_BYTES);
    cudaFuncSetAttribute(k2_ffn1, cudaFuncAttributeMaxDynamicSharedMemorySize, SM2_BYTES);
    cudaFuncSetAttribute(k4_ffn2, cudaFuncAttributeMaxDynamicSharedMemorySize, SM4_BYTES);

    k1_attn<<<4096, 256, SM1_BYTES>>>(x, l0, n1w, n1b, qkvw, gw, gb, pw, pb, out);
    k2_ffn1<<<4096, 256, SM2_BYTES>>>(out, n2w, n2b, w1, b1);
    dim3 g3(8, 32, 2048);
    k3_dw<<<g3, 256>>>(dw, dwb);
    k4_ffn2<<<4096, 256, SM4_BYTES>>>(w2, b2, out);
}

// round 6
// speedup vs baseline: 1.2896x; 1.2896x over previous
#include <cuda_runtime.h>
#include <math.h>

// ---------------------------------------------------------------------------
// IGAB block, B=4, C=128, H=W=256, window 8x8, heads=8, head_dim=16, HIDDEN=512
// f32x2 (FFMA2) packed-pair GEMMs:
//   k1: LN1 + QKV + gate + window-attention + proj + residual  -> d_out
//   k2: LN2 + W1 + GELU (128px x 512out tiles, 8x8 blocking)   -> g_h1
//   k3: depthwise 3x3 + bias + GELU                            -> g_h2
//   k4: W2 + bias + residual (128px x 128out, K=512)           -> d_out
// ---------------------------------------------------------------------------

#define HW 65536
#define NPLANE 256

__device__ float g_h1[(size_t)4 * 512 * HW];
__device__ float g_h2[(size_t)4 * 512 * HW];

typedef unsigned long long u64;

__device__ __forceinline__ u64 ffma2(u64 a, u64 b, u64 c) {
    u64 d;
    asm("fma.rn.f32x2 %0, %1, %2, %3;" : "=l"(d) : "l"(a), "l"(b), "l"(c));
    return d;
}
__device__ __forceinline__ u64 pack2(float v) {
    u64 d;
    asm("mov.b64 %0, {%1, %1};" : "=l"(d) : "r"(__float_as_uint(v)));
    return d;
}
__device__ __forceinline__ float2 unpack2(u64 v) {
    unsigned lo, hi;
    asm("mov.b64 {%0, %1}, %2;" : "=r"(lo), "=r"(hi) : "l"(v));
    return make_float2(__uint_as_float(lo), __uint_as_float(hi));
}
__device__ __forceinline__ float gelu_exact(float v) {
    return 0.5f * v * (1.0f + erff(v * 0.70710678118654752f));
}

// ----- kernel 1 shared layout (floats) -----
#define OFF_A   0
#define OFF_B   8704
#define OFF_Q   17408
#define OFF_K   26112
#define OFF_V   34816
#define OFF_W   43520
#define OFF_S   51968
#define OFF_L0  56320
#define OFF_MU  56384
#define OFF_RS  56448
#define OFF_DEN 56512
#define SM1_FLOATS 56576
#define SM1_BYTES (SM1_FLOATS * 4)

__global__ __launch_bounds__(256, 1)
void k1_attn(const float* __restrict__ x, const float* __restrict__ l0,
             const float* __restrict__ n1w, const float* __restrict__ n1b,
             const float* __restrict__ qkvw, const float* __restrict__ gw,
             const float* __restrict__ gb, const float* __restrict__ pw,
             const float* __restrict__ pb, float* __restrict__ outp)
{
    extern __shared__ float sm[];
    const int tid = threadIdx.x;
    const int wi = blockIdx.x;
    const int b  = wi >> 10;
    const int hi = (wi >> 5) & 31;
    const int wj = wi & 31;
    const int base_pix = (hi * 8) * NPLANE + wj * 8;
    const float* xb = x + (size_t)b * 128 * HW;

    #pragma unroll
    for (int it = 0; it < 32; ++it) {
        int idx = tid + it * 256;
        int c = idx >> 6, p = idx & 63;
        sm[OFF_A + c * 68 + p] = xb[c * HW + base_pix + (p >> 3) * NPLANE + (p & 7)];
    }
    if (tid < 64) {
        int p = tid;
        sm[OFF_L0 + p] = l0[(size_t)b * HW + base_pix + (p >> 3) * NPLANE + (p & 7)];
    }
    __syncthreads();

    {   // LN1 stats
        int p = tid >> 2, part = tid & 3;
        float s = 0.f, sq = 0.f;
        #pragma unroll
        for (int c = part * 32; c < part * 32 + 32; ++c) {
            float v = sm[OFF_A + c * 68 + p];
            s += v; sq += v * v;
        }
        s  += __shfl_xor_sync(0xffffffffu, s, 1);
        sq += __shfl_xor_sync(0xffffffffu, sq, 1);
        s  += __shfl_xor_sync(0xffffffffu, s, 2);
        sq += __shfl_xor_sync(0xffffffffu, sq, 2);
        if (part == 0) {
            float mu = s * (1.f / 128.f);
            float var = sq * (1.f / 128.f) - mu * mu;
            sm[OFF_MU + p] = mu;
            sm[OFF_RS + p] = rsqrtf(var + 1e-6f);
        }
    }
    __syncthreads();
    #pragma unroll
    for (int it = 0; it < 32; ++it) {
        int idx = tid + it * 256;
        int c = idx >> 6, p = idx & 63;
        sm[OFF_B + c * 68 + p] =
            n1w[c] * (sm[OFF_A + c * 68 + p] - sm[OFF_MU + p]) * sm[OFF_RS + p] + n1b[c];
    }
    __syncthreads();

    const int tx = tid & 15, ty = tid >> 4;

    // ---- QKV: 6 chunks of 64 outs, f32x2 pairs ----
    for (int ch = 0; ch < 6; ++ch) {
        #pragma unroll
        for (int it = 0; it < 32; ++it) {
            int idx = tid + it * 256;
            int ol = idx >> 7, c = idx & 127;
            sm[OFF_W + ol * 132 + c] = qkvw[(ch * 64 + ol) * 128 + c];
        }
        __syncthreads();
        u64 acc[2][4];
        #pragma unroll
        for (int i = 0; i < 2; ++i)
            #pragma unroll
            for (int j = 0; j < 4; ++j) acc[i][j] = 0ull;
        #pragma unroll 4
        for (int c = 0; c < 128; ++c) {
            ulonglong2 xv = *(const ulonglong2*)&sm[OFF_B + c * 68 + 4 * tx];
            #pragma unroll
            for (int j = 0; j < 4; ++j) {
                u64 wp = pack2(sm[OFF_W + (4 * ty + j) * 132 + c]);
                acc[0][j] = ffma2(xv.x, wp, acc[0][j]);
                acc[1][j] = ffma2(xv.y, wp, acc[1][j]);
            }
        }
        int dst = (ch < 2) ? OFF_Q : (ch < 4) ? OFF_K : OFF_V;
        int rbase = (ch & 1) * 64;
        if (ch < 2) {
            #pragma unroll
            for (int j = 0; j < 4; ++j) {
                int o = rbase + 4 * ty + j;
                float gwv = gw[o], gbv = gb[o];
                float2 f0 = unpack2(acc[0][j]), f1 = unpack2(acc[1][j]);
                float f[4] = {f0.x, f0.y, f1.x, f1.y};
                float4 st;
                float* pst = &st.x;
                #pragma unroll
                for (int i = 0; i < 4; ++i) {
                    int p = 4 * tx + i;
                    float z = sm[OFF_L0 + p] * gwv + gbv;
                    float g = 1.f / (1.f + __expf(-z));
                    pst[i] = f[i] * g;
                }
                *(float4*)&sm[dst + o * 68 + 4 * tx] = st;
            }
        } else {
            #pragma unroll
            for (int j = 0; j < 4; ++j) {
                int o = rbase + 4 * ty + j;
                float2 f0 = unpack2(acc[0][j]), f1 = unpack2(acc[1][j]);
                float4 st = {f0.x, f0.y, f1.x, f1.y};
                *(float4*)&sm[dst + o * 68 + 4 * tx] = st;
            }
        }
        __syncthreads();
    }

    // ---- window attention, head-sequential ----
    for (int h = 0; h < 8; ++h) {
        const int cb = h * 16;
        {   // S = scale * Q K^T (f32x2 over px pairs)
            u64 acc[2][4];
            #pragma unroll
            for (int i = 0; i < 2; ++i)
                #pragma unroll
                for (int j = 0; j < 4; ++j) acc[i][j] = 0ull;
            #pragma unroll
            for (int d = 0; d < 16; ++d) {
                ulonglong2 qv = *(const ulonglong2*)&sm[OFF_Q + (cb + d) * 68 + 4 * tx];
                #pragma unroll
                for (int j = 0; j < 4; ++j) {
                    u64 kp = pack2(sm[OFF_K + (cb + d) * 68 + 4 * ty + j]);
                    acc[0][j] = ffma2(qv.x, kp, acc[0][j]);
                    acc[1][j] = ffma2(qv.y, kp, acc[1][j]);
                }
            }
            #pragma unroll
            for (int a = 0; a < 2; ++a)
                #pragma unroll
                for (int j = 0; j < 4; ++j) {
                    float2 f = unpack2(acc[a][j]);
                    sm[OFF_S + (4 * tx + 2 * a) * 68 + 4 * ty + j] = f.x * 0.25f;
                    sm[OFF_S + (4 * tx + 2 * a + 1) * 68 + 4 * ty + j] = f.y * 0.25f;
                }
        }
        __syncthreads();
        {   // softmax rows
            int r = tid >> 2, part = tid & 3;
            float m = -1e30f;
            #pragma unroll
            for (int kk = part * 16; kk < part * 16 + 16; ++kk)
                m = fmaxf(m, sm[OFF_S + r * 68 + kk]);
            m = fmaxf(m, __shfl_xor_sync(0xffffffffu, m, 1));
            m = fmaxf(m, __shfl_xor_sync(0xffffffffu, m, 2));
            float s = 0.f;
            #pragma unroll
            for (int kk = part * 16; kk < part * 16 + 16; ++kk) {
                float e = __expf(sm[OFF_S + r * 68 + kk] - m);
                sm[OFF_S + r * 68 + kk] = e;
                s += e;
            }
            s += __shfl_xor_sync(0xffffffffu, s, 1);
            s += __shfl_xor_sync(0xffffffffu, s, 2);
            if (part == 0) sm[OFF_DEN + r] = 1.f / s;
        }
        __syncthreads();
        {   // O = P V, f32x2 over the kk reduction (pairs), horizontal add at end
            int pq = tid >> 2, dg = tid & 3;
            const u64* Srow = (const u64*)&sm[OFF_S + pq * 68];
            const u64* V0 = (const u64*)&sm[OFF_V + (cb + 4 * dg + 0) * 68];
            const u64* V1 = (const u64*)&sm[OFF_V + (cb + 4 * dg + 1) * 68];
            const u64* V2 = (const u64*)&sm[OFF_V + (cb + 4 * dg + 2) * 68];
            const u64* V3 = (const u64*)&sm[OFF_V + (cb + 4 * dg + 3) * 68];
            u64 a0 = 0ull, a1 = 0ull, a2 = 0ull, a3 = 0ull;
            #pragma unroll 8
            for (int kk = 0; kk < 32; ++kk) {
                u64 prp = Srow[kk];
                a0 = ffma2(prp, V0[kk], a0);
                a1 = ffma2(prp, V1[kk], a1);
                a2 = ffma2(prp, V2[kk], a2);
                a3 = ffma2(prp, V3[kk], a3);
            }
            float dn = sm[OFF_DEN + pq];
            float2 f0 = unpack2(a0), f1 = unpack2(a1), f2 = unpack2(a2), f3 = unpack2(a3);
            sm[OFF_B + (cb + 4 * dg + 0) * 68 + pq] = (f0.x + f0.y) * dn;
            sm[OFF_B + (cb + 4 * dg + 1) * 68 + pq] = (f1.x + f1.y) * dn;
            sm[OFF_B + (cb + 4 * dg + 2) * 68 + pq] = (f2.x + f2.y) * dn;
            sm[OFF_B + (cb + 4 * dg + 3) * 68 + pq] = (f3.x + f3.y) * dn;
        }
        __syncthreads();
    }

    // ---- proj + bias + residual ----
    for (int ch = 0; ch < 2; ++ch) {
        #pragma unroll
        for (int it = 0; it < 32; ++it) {
            int idx = tid + it * 256;
            int ol = idx >> 7, c = idx & 127;
            sm[OFF_W + ol * 132 + c] = pw[(ch * 64 + ol) * 128 + c];
        }
        __syncthreads();
        u64 acc[2][4];
        #pragma unroll
        for (int i = 0; i < 2; ++i)
            #pragma unroll
            for (int j = 0; j < 4; ++j) acc[i][j] = 0ull;
        #pragma unroll 4
        for (int c = 0; c < 128; ++c) {
            ulonglong2 xv = *(const ulonglong2*)&sm[OFF_B + c * 68 + 4 * tx];
            #pragma unroll
            for (int j = 0; j < 4; ++j) {
                u64 wp = pack2(sm[OFF_W + (4 * ty + j) * 132 + c]);
                acc[0][j] = ffma2(xv.x, wp, acc[0][j]);
                acc[1][j] = ffma2(xv.y, wp, acc[1][j]);
            }
        }
        #pragma unroll
        for (int j = 0; j < 4; ++j) {
            float2 f0 = unpack2(acc[0][j]), f1 = unpack2(acc[1][j]);
            float4 st = {f0.x, f0.y, f1.x, f1.y};
            *(float4*)&sm[OFF_S + (4 * ty + j) * 68 + 4 * tx] = st;
        }
        __syncthreads();
        #pragma unroll
        for (int it = 0; it < 16; ++it) {
            int idx = tid + it * 256;
            int ol = idx >> 6, p = idx & 63;
            int o = ch * 64 + ol;
            float v = sm[OFF_S + ol * 68 + p] + pb[o] + sm[OFF_A + o * 68 + p];
            outp[(size_t)(b * 128 + o) * HW + base_pix + (p >> 3) * NPLANE + (p & 7)] = v;
        }
        __syncthreads();
    }
}

// ----- kernel 2: LN2 + W1(128->512) + GELU, 128px tiles, f32x2 -----
#define SM2_XS 0
#define SM2_WS 16640            // 128*130
#define SM2_MU 33536            // +128*132
#define SM2_RS 33664
#define SM2_FLOATS 33792
#define SM2_BYTES (SM2_FLOATS * 4)

__global__ __launch_bounds__(256, 1)
void k2_ffn1(const float* __restrict__ inp, const float* __restrict__ n2w,
             const float* __restrict__ n2b, const float* __restrict__ w1,
             const float* __restrict__ b1)
{
    extern __shared__ float sm[];
    const int tid = threadIdx.x;
    const int pg = blockIdx.x * 128;
    const int b = pg >> 16;
    const int pix = pg & 65535;
    const float* ib = inp + (size_t)b * 128 * HW + pix;

    #pragma unroll
    for (int it = 0; it < 64; ++it) {
        int idx = tid + it * 256;
        int c = idx >> 7, p = idx & 127;
        sm[SM2_XS + c * 130 + p] = ib[c * HW + p];
    }
    __syncthreads();
    {   // LN stats: 2 threads / pixel
        int p = tid >> 1, part = tid & 1;
        float s = 0.f, sq = 0.f;
        #pragma unroll
        for (int c = part * 64; c < part * 64 + 64; ++c) {
            float v = sm[SM2_XS + c * 130 + p];
            s += v; sq += v * v;
        }
        s  += __shfl_xor_sync(0xffffffffu, s, 1);
        sq += __shfl_xor_sync(0xffffffffu, sq, 1);
        if (part == 0) {
            float mu = s * (1.f / 128.f);
            float var = sq * (1.f / 128.f) - mu * mu;
            sm[SM2_MU + p] = mu;
            sm[SM2_RS + p] = rsqrtf(var + 1e-6f);
        }
    }
    __syncthreads();
    #pragma unroll
    for (int it = 0; it < 64; ++it) {
        int idx = tid + it * 256;
        int c = idx >> 7, p = idx & 127;
        sm[SM2_XS + c * 130 + p] =
            n2w[c] * (sm[SM2_XS + c * 130 + p] - sm[SM2_MU + p]) * sm[SM2_RS + p] + n2b[c];
    }

    const int tx = tid & 15, ty = tid >> 4;
    for (int ch = 0; ch < 4; ++ch) {
        __syncthreads();
        #pragma unroll
        for (int it = 0; it < 64; ++it) {
            int idx = tid + it * 256;
            int o = idx >> 7, c = idx & 127;
            sm[SM2_WS + o * 132 + c] = w1[(ch * 128 + o) * 128 + c];
        }
        __syncthreads();

        u64 acc[4][8];
        #pragma unroll
        for (int i = 0; i < 4; ++i)
            #pragma unroll
            for (int j = 0; j < 8; ++j) acc[i][j] = 0ull;
        #pragma unroll 2
        for (int c = 0; c < 128; ++c) {
            u64 xp[4];
            #pragma unroll
            for (int i = 0; i < 4; ++i)
                xp[i] = *(const u64*)&sm[SM2_XS + c * 130 + 2 * tx + 32 * i];
            #pragma unroll
            for (int j = 0; j < 8; ++j) {
                u64 wp = pack2(sm[SM2_WS + (8 * ty + j) * 132 + c]);
                #pragma unroll
                for (int i = 0; i < 4; ++i) acc[i][j] = ffma2(xp[i], wp, acc[i][j]);
            }
        }
        #pragma unroll
        for (int j = 0; j < 8; ++j) {
            int o = ch * 128 + 8 * ty + j;
            float bv = b1[o];
            float* ob = &g_h1[(size_t)(b * 512 + o) * HW + pix];
            #pragma unroll
            for (int i = 0; i < 4; ++i) {
                float2 f = unpack2(acc[i][j]);
                float2 r = {gelu_exact(f.x + bv), gelu_exact(f.y + bv)};
                *(float2*)&ob[2 * tx + 32 * i] = r;
            }
        }
    }
}

// ----- kernel 3: depthwise 3x3 + bias + GELU -----
__global__ __launch_bounds__(256)
void k3_dw(const float* __restrict__ dw, const float* __restrict__ dwb)
{
    __shared__ float tile[10][34];
    const int plane = blockIdx.z;
    const int ch = plane & 511;
    const float* ip = g_h1 + (size_t)plane * HW;
    float* op = g_h2 + (size_t)plane * HW;
    const int x0 = blockIdx.x * 32, y0 = blockIdx.y * 8;
    const int tid = threadIdx.x;

    for (int idx = tid; idx < 340; idx += 256) {
        int ly = idx / 34, lx = idx % 34;
        int gy = y0 + ly - 1, gx = x0 + lx - 1;
        tile[ly][lx] = (gy >= 0 && gy < 256 && gx >= 0 && gx < 256) ? ip[gy * NPLANE + gx] : 0.f;
    }
    __syncthreads();

    const int tx = tid & 31, ty = tid >> 5;
    float w[9];
    #pragma unroll
    for (int i = 0; i < 9; ++i) w[i] = dw[ch * 9 + i];
    float s = dwb[ch];
    #pragma unroll
    for (int dy = 0; dy < 3; ++dy)
        #pragma unroll
        for (int dx = 0; dx < 3; ++dx)
            s += w[dy * 3 + dx] * tile[ty + dy][tx + dx];
    op[(y0 + ty) * NPLANE + x0 + tx] = gelu_exact(s);
}

// ----- kernel 4: W2(512->128) + bias + residual, 128px tiles, f32x2 -----
#define SM4_HS 0
#define SM4_WS 16640            // 128*130
#define SM4_FLOATS 33536        // +128*132
#define SM4_BYTES (SM4_FLOATS * 4)

__global__ __launch_bounds__(256, 1)
void k4_ffn2(const float* __restrict__ w2, const float* __restrict__ b2,
             float* __restrict__ io)
{
    extern __shared__ float sm[];
    const int tid = threadIdx.x;
    const int pg = blockIdx.x * 128;
    const int b = pg >> 16;
    const int pix = pg & 65535;
    const float* hb = g_h2 + (size_t)b * 512 * HW + pix;

    const int tx = tid & 15, ty = tid >> 4;
    u64 acc[4][8];
    #pragma unroll
    for (int i = 0; i < 4; ++i)
        #pragma unroll
        for (int j = 0; j < 8; ++j) acc[i][j] = 0ull;

    for (int kch = 0; kch < 4; ++kch) {
        __syncthreads();
        #pragma unroll
        for (int it = 0; it < 64; ++it) {
            int idx = tid + it * 256;
            int c = idx >> 7, p = idx & 127;
            sm[SM4_HS + c * 130 + p] = hb[(size_t)(kch * 128 + c) * HW + p];
        }
        #pragma unroll
        for (int it = 0; it < 64; ++it) {
            int idx = tid + it * 256;
            int o = idx >> 7, c = idx & 127;
            sm[SM4_WS + o * 132 + c] = w2[o * 512 + kch * 128 + c];
        }
        __syncthreads();
        #pragma unroll 2
        for (int c = 0; c < 128; ++c) {
            u64 xp[4];
            #pragma unroll
            for (int i = 0; i < 4; ++i)
                xp[i] = *(const u64*)&sm[SM4_HS + c * 130 + 2 * tx + 32 * i];
            #pragma unroll
            for (int j = 0; j < 8; ++j) {
                u64 wp = pack2(sm[SM4_WS + (8 * ty + j) * 132 + c]);
                #pragma unroll
                for (int i = 0; i < 4; ++i) acc[i][j] = ffma2(xp[i], wp, acc[i][j]);
            }
        }
    }

    #pragma unroll
    for (int j = 0; j < 8; ++j) {
        int o = 8 * ty + j;
        float bv = b2[o];
        float* ob = &io[(size_t)(b * 128 + o) * HW + pix];
        #pragma unroll
        for (int i = 0; i < 4; ++i) {
            float2 f = unpack2(acc[i][j]);
            float2 r = *(float2*)&ob[2 * tx + 32 * i];
            r.x += f.x + bv;
            r.y += f.y + bv;
            *(float2*)&ob[2 * tx + 32 * i] = r;
        }
    }
}

// ---------------------------------------------------------------------------
extern "C" void kernel_launch(void* const* d_in, const int* in_sizes, int n_in,
                              void* d_out, int out_size)
{
    const float* x    = (const float*)d_in[0];
    const float* l0   = (const float*)d_in[1];
    const float* n1w  = (const float*)d_in[2];
    const float* n1b  = (const float*)d_in[3];
    const float* n2w  = (const float*)d_in[4];
    const float* n2b  = (const float*)d_in[5];
    const float* qkvw = (const float*)d_in[6];
    const float* gw   = (const float*)d_in[7];
    const float* gb   = (const float*)d_in[8];
    const float* pw   = (const float*)d_in[9];
    const float* pb   = (const float*)d_in[10];
    const float* w1   = (const float*)d_in[11];
    const float* b1   = (const float*)d_in[12];
    const float* dw   = (const float*)d_in[13];
    const float* dwb  = (const float*)d_in[14];
    const float* w2   = (const float*)d_in[15];
    const float* b2   = (const float*)d_in[16];
    float* out = (float*)d_out;

    cudaFuncSetAttribute(k1_attn, cudaFuncAttributeMaxDynamicSharedMemorySize, SM1_BYTES);
    cudaFuncSetAttribute(k2_ffn1, cudaFuncAttributeMaxDynamicSharedMemorySize, SM2_BYTES);
    cudaFuncSetAttribute(k4_ffn2, cudaFuncAttributeMaxDynamicSharedMemorySize, SM4_BYTES);

    k1_attn<<<4096, 256, SM1_BYTES>>>(x, l0, n1w, n1b, qkvw, gw, gb, pw, pb, out);
    k2_ffn1<<<2048, 256, SM2_BYTES>>>(out, n2w, n2b, w1, b1);
    dim3 g3(8, 32, 2048);
    k3_dw<<<g3, 256>>>(dw, dwb);
    k4_ffn2<<<2048, 256, SM4_BYTES>>>(w2, b2, out);
}